// round 12
// baseline (speedup 1.0000x reference)
#include <cuda_runtime.h>
#include <cuda_bf16.h>
#include <mma.h>
#include <math.h>
#include <stdint.h>

using namespace nvcuda;

#define Bdim 128
#define Tdim 512
#define Idim 300
#define Hdim 256
#define G4H  1024   // 4*H gate rows
#define NSTEP 512

#define KBLK 5      // K padded 300 -> 320 = 5 blocks of 64 bf16
#define GPITCH 72   // smem pitch (bf16 elems) for gemm_wmma tiles

// ---------------------------------------------------------------------------
// Scratch (static __device__ globals; no allocation anywhere)
// ---------------------------------------------------------------------------
__device__ float g_xp[(size_t)Bdim * Tdim * G4H];   // 256 MB: x @ W_ih_f^T (no bias)
__device__ float g_xpb[Bdim * G4H];                 // backward projection at t=T-1
__device__ float g_h[2][Bdim][Hdim];                // final hidden state (parity 0)
__device__ unsigned int g_bar[16];                  // legacy (zeroed, unused)

// packed bf16 hi/lo operand tiles, plain linear layout:
__device__ uint4 g_Ah[(size_t)512 * KBLK * 1024];
__device__ uint4 g_Al[(size_t)512 * KBLK * 1024];
__device__ uint4 g_Bh[8 * KBLK * 1024];
__device__ uint4 g_Bl[8 * KBLK * 1024];

// ---------------------------------------------------------------------------
__device__ __forceinline__ uint32_t smem_u32(const void* p) {
    uint32_t a;
    asm("{ .reg .u64 t; cvta.to.shared.u64 t, %1; cvt.u32.u64 %0, t; }"
        : "=r"(a) : "l"(p));
    return a;
}

// ---------------------------------------------------------------------------
__global__ void init_k()
{
    int i = blockIdx.x * blockDim.x + threadIdx.x;
    if (i < Bdim * Hdim) ((float*)g_h)[i] = 0.f;
    if (i < 16) g_bar[i] = 0u;
}

// ---------------------------------------------------------------------------
// conv_pack: fp32 rows [rows x Idim] -> bf16 hi/lo packed tiles (linear).
// ---------------------------------------------------------------------------
__global__ void conv_pack(const float* __restrict__ src, int rows,
                          uint4* __restrict__ Hc, uint4* __restrict__ Lc)
{
    int id = blockIdx.x * blockDim.x + threadIdx.x;
    int total = rows * 40;
    if (id >= total) return;
    int m  = id / 40;
    int g  = id % 40;
    int k0 = g * 8;

    union U8 { uint4 u; __nv_bfloat16 b[8]; } hu, lu;
#pragma unroll
    for (int j = 0; j < 8; j++) {
        int k = k0 + j;
        float v = (k < Idim) ? src[(size_t)m * Idim + k] : 0.f;
        __nv_bfloat16 h = __float2bfloat16(v);
        hu.b[j] = h;
        lu.b[j] = __float2bfloat16(v - __bfloat162float(h));
    }

    int tile = m >> 7;
    int r    = m & 127;
    int blk  = k0 >> 6;
    int c8   = (k0 & 63) >> 3;
    size_t idx = ((size_t)tile * KBLK + blk) * 1024 + (size_t)r * 8 + c8;
    Hc[idx] = hu.u;
    Lc[idx] = lu.u;
}

// ---------------------------------------------------------------------------
// gemm_wmma — EXACT R6 version (490 us passing): xp = x @ W_ih_f^T, split-bf16
// ---------------------------------------------------------------------------
#define GEMM_SMEM (4 * 128 * GPITCH * 2)

__global__ void __launch_bounds__(256) gemm_wmma(
    const uint4* __restrict__ Ah, const uint4* __restrict__ Al,
    const uint4* __restrict__ Bh, const uint4* __restrict__ Bl,
    float* __restrict__ C)
{
    extern __shared__ __nv_bfloat16 sm[];
    __nv_bfloat16* sAh = sm;
    __nv_bfloat16* sAl = sm + 128 * GPITCH;
    __nv_bfloat16* sBh = sm + 2 * 128 * GPITCH;
    __nv_bfloat16* sBl = sm + 3 * 128 * GPITCH;

    int tid = threadIdx.x;
    int wid = tid >> 5;
    int wm  = wid >> 2;
    int wn  = wid & 3;
    int nt  = blockIdx.x;
    int mt  = blockIdx.y;

    wmma::fragment<wmma::accumulator, 16, 16, 16, float> acc[4][2];
#pragma unroll
    for (int i = 0; i < 4; i++)
#pragma unroll
        for (int j = 0; j < 2; j++) wmma::fill_fragment(acc[i][j], 0.f);

    for (int blk = 0; blk < KBLK; blk++) {
        const uint4* gA_h = Ah + ((size_t)mt * KBLK + blk) * 1024;
        const uint4* gA_l = Al + ((size_t)mt * KBLK + blk) * 1024;
        const uint4* gB_h = Bh + ((size_t)nt * KBLK + blk) * 1024;
        const uint4* gB_l = Bl + ((size_t)nt * KBLK + blk) * 1024;
        uint4* dAh = (uint4*)sAh;
        uint4* dAl = (uint4*)sAl;
        uint4* dBh = (uint4*)sBh;
        uint4* dBl = (uint4*)sBl;
#pragma unroll
        for (int it = 0; it < 4; it++) {
            int i = it * 256 + tid;
            int r = i >> 3, c = i & 7;
            int d = r * 9 + c;
            dAh[d] = gA_h[i];
            dAl[d] = gA_l[i];
            dBh[d] = gB_h[i];
            dBl[d] = gB_l[i];
        }
        __syncthreads();

#pragma unroll
        for (int prod = 0; prod < 3; prod++) {
            const __nv_bfloat16* As = (prod == 2) ? sAl : sAh;
            const __nv_bfloat16* Bs = (prod == 1) ? sBl : sBh;
#pragma unroll
            for (int ks = 0; ks < 4; ks++) {
                wmma::fragment<wmma::matrix_a, 16, 16, 16, __nv_bfloat16,
                               wmma::row_major> af[4];
                wmma::fragment<wmma::matrix_b, 16, 16, 16, __nv_bfloat16,
                               wmma::col_major> bfr[2];
#pragma unroll
                for (int i = 0; i < 4; i++)
                    wmma::load_matrix_sync(
                        af[i], As + (wm * 64 + i * 16) * GPITCH + ks * 16, GPITCH);
#pragma unroll
                for (int j = 0; j < 2; j++)
                    wmma::load_matrix_sync(
                        bfr[j], Bs + (wn * 32 + j * 16) * GPITCH + ks * 16, GPITCH);
#pragma unroll
                for (int i = 0; i < 4; i++)
#pragma unroll
                    for (int j = 0; j < 2; j++)
                        wmma::mma_sync(acc[i][j], af[i], bfr[j], acc[i][j]);
            }
        }
        __syncthreads();
    }

    size_t row0 = (size_t)mt * 128 + wm * 64;
    int    col0 = nt * 128 + wn * 32;
#pragma unroll
    for (int i = 0; i < 4; i++)
#pragma unroll
        for (int j = 0; j < 2; j++)
            wmma::store_matrix_sync(
                C + (row0 + i * 16) * G4H + col0 + j * 16,
                acc[i][j], G4H, wmma::mem_row_major);
}

// ---------------------------------------------------------------------------
// fp32 SGEMM (tiny backward projection at t = T-1; includes bias)
// ---------------------------------------------------------------------------
__global__ void __launch_bounds__(256) sgemm_bias(
    const float* __restrict__ A, long lda,
    const float* __restrict__ W,
    const float* __restrict__ bias,
    float* __restrict__ C)
{
    __shared__ float As[8][128];
    __shared__ float Bs[8][128];
    int tid  = threadIdx.x;
    long row0 = (long)blockIdx.y * 128;
    int  col0 = blockIdx.x * 128;
    int  lm = tid >> 1;
    int  lk = (tid & 1) * 4;
    int  tx = tid & 15, ty = tid >> 4;

    float bsv[8];
    *(float4*)(bsv)     = *(const float4*)&bias[col0 + tx * 8];
    *(float4*)(bsv + 4) = *(const float4*)&bias[col0 + tx * 8 + 4];

    float acc[8][8];
#pragma unroll
    for (int i = 0; i < 8; i++)
#pragma unroll
        for (int j = 0; j < 8; j++) acc[i][j] = 0.f;

    for (int k0 = 0; k0 < Idim; k0 += 8) {
        float4 av = make_float4(0.f, 0.f, 0.f, 0.f);
        float4 bv = make_float4(0.f, 0.f, 0.f, 0.f);
        if (k0 + lk < Idim) {
            av = *(const float4*)(A + (row0 + lm) * lda + k0 + lk);
            bv = *(const float4*)(W + (long)(col0 + lm) * Idim + k0 + lk);
        }
        __syncthreads();
        As[lk + 0][lm] = av.x; As[lk + 1][lm] = av.y;
        As[lk + 2][lm] = av.z; As[lk + 3][lm] = av.w;
        Bs[lk + 0][lm] = bv.x; Bs[lk + 1][lm] = bv.y;
        Bs[lk + 2][lm] = bv.z; Bs[lk + 3][lm] = bv.w;
        __syncthreads();
#pragma unroll
        for (int k = 0; k < 8; k++) {
            float a[8], b[8];
            *(float4*)(a)     = *(const float4*)&As[k][ty * 8];
            *(float4*)(a + 4) = *(const float4*)&As[k][ty * 8 + 4];
            *(float4*)(b)     = *(const float4*)&Bs[k][tx * 8];
            *(float4*)(b + 4) = *(const float4*)&Bs[k][tx * 8 + 4];
#pragma unroll
            for (int i = 0; i < 8; i++)
#pragma unroll
                for (int j = 0; j < 8; j++)
                    acc[i][j] = fmaf(a[i], b[j], acc[i][j]);
        }
    }

#pragma unroll
    for (int i = 0; i < 8; i++) {
        long r = row0 + ty * 8 + i;
        float4 o0 = make_float4(acc[i][0] + bsv[0], acc[i][1] + bsv[1],
                                acc[i][2] + bsv[2], acc[i][3] + bsv[3]);
        float4 o1 = make_float4(acc[i][4] + bsv[4], acc[i][5] + bsv[5],
                                acc[i][6] + bsv[6], acc[i][7] + bsv[7]);
        *(float4*)&C[r * G4H + col0 + tx * 8]     = o0;
        *(float4*)&C[r * G4H + col0 + tx * 8 + 4] = o1;
    }
}

// ---------------------------------------------------------------------------
// Persistent forward LSTM recurrence — R6 compute structure (proven FFMA GEMM
// + k-split partials + reduce) with the h-exchange swapped to cluster DSMEM:
//   * 8 CTAs of a batch group form one cluster (rank = col group gj)
//   * each thread PUSHES its new h into all 8 CTAs' hsh[q] via st.shared::cluster
//   * sync = 2 parity mbarriers (count 8): tid0 fence.acq_rel.cluster + arrive
//     on every CTA's mbar[q]; all threads try_wait.parity.acquire.cluster
// No global h traffic, no atomic spin, no per-step 8KB h load phase.
// ---------------------------------------------------------------------------
#define WPITCH 129
#define SMEM_FLOATS (Hdim * WPITCH + 2 * 8 * Hdim + 8 * G4H)
#define SMEM_BYTES  (SMEM_FLOATS * 4)

__device__ __forceinline__ float sigf(float x) { return 1.f / (1.f + __expf(-x)); }

__global__ void __launch_bounds__(256, 1) __cluster_dims__(8, 1, 1)
lstm_fwd(const float* __restrict__ Whh, const float* __restrict__ bias)
{
    extern __shared__ float sm_f[];
    float* Wsh  = sm_f;                        // [256][129] transposed W tile
    float* hsh  = sm_f + Hdim * WPITCH;        // [2][8][256] parity h buffers
    float* part = hsh + 2 * 8 * Hdim;          // [8][1024]  k-split partials

    __shared__ __align__(8) unsigned long long s_mbar[2];

    int tid = threadIdx.x;
    int gb  = blockIdx.x >> 3;                 // batch group 0..15
    int gj  = blockIdx.x & 7;                  // cluster rank = col group
    int b0  = gb * 8;
    int j0  = gj * 32;

    for (int idx = tid; idx < 128 * Hdim; idx += 256) {
        int lr = idx >> 8;
        int k  = idx & 255;
        int grow = ((lr >> 5) << 8) + j0 + (lr & 31);
        Wsh[k * WPITCH + lr] = Whh[grow * Hdim + k];
    }
    for (int i = tid; i < 2 * 8 * Hdim; i += 256) hsh[i] = 0.f;

    uint32_t mbar_base = smem_u32(&s_mbar[0]);
    uint32_t hsh_base  = smem_u32(hsh);
    if (tid == 0) {
        asm volatile("mbarrier.init.shared.b64 [%0], 8;" :: "r"(mbar_base) : "memory");
        asm volatile("mbarrier.init.shared.b64 [%0], 8;" :: "r"(mbar_base + 8) : "memory");
    }
    __syncthreads();
    // all CTAs' mbarriers + zeroed buffers visible before any push/arrive
    asm volatile("barrier.cluster.arrive.aligned;" ::: "memory");
    asm volatile("barrier.cluster.wait.aligned;"  ::: "memory");

    int ks    = tid >> 5;
    int lane  = tid & 31;
    int bg    = lane >> 4;
    int r8    = lane & 15;
    int kbase = ks * 32;
    int bred  = tid >> 5;
    int jj    = tid & 31;

    float bgate[4];
#pragma unroll
    for (int g = 0; g < 4; g++) bgate[g] = bias[g * 256 + j0 + jj];

    float c = 0.f;
    int ph0 = 0, ph1 = 0;                      // parity-phase trackers

    for (int t = 0; t < NSTEP; t++) {
        float xg[4];
        {
            size_t base = ((size_t)(b0 + bred) * Tdim + t) * G4H + j0 + jj;
#pragma unroll
            for (int g = 0; g < 4; g++) xg[g] = g_xp[base + (size_t)g * 256];
        }

        int p = t & 1;
        int q = p ^ 1;
        const float* hp = hsh + p * 8 * Hdim;

        // GEMM slice (EXACT R6 inner loop)
        float acc[4][8];
#pragma unroll
        for (int bi = 0; bi < 4; bi++)
#pragma unroll
            for (int i = 0; i < 8; i++) acc[bi][i] = 0.f;

#pragma unroll
        for (int k = 0; k < 32; k += 4) {
            float4 hv[4];
#pragma unroll
            for (int bi = 0; bi < 4; bi++)
                hv[bi] = *(const float4*)&hp[(bg * 4 + bi) * Hdim + kbase + k];
#pragma unroll
            for (int kk = 0; kk < 4; kk++) {
                const float* wr = &Wsh[(kbase + k + kk) * WPITCH + r8];
                float w[8];
#pragma unroll
                for (int i = 0; i < 8; i++) w[i] = wr[i * 16];
#pragma unroll
                for (int bi = 0; bi < 4; bi++) {
                    float hval = ((const float*)&hv[bi])[kk];
#pragma unroll
                    for (int i = 0; i < 8; i++)
                        acc[bi][i] = fmaf(hval, w[i], acc[bi][i]);
                }
            }
        }

#pragma unroll
        for (int bi = 0; bi < 4; bi++)
#pragma unroll
            for (int i = 0; i < 8; i++)
                part[ks * G4H + (bg * 4 + bi) * 128 + (r8 + 16 * i)] = acc[bi][i];
        __syncthreads();

        float gsum[4];
#pragma unroll
        for (int g = 0; g < 4; g++) {
            float s = xg[g] + bgate[g];
#pragma unroll
            for (int kss = 0; kss < 8; kss++)
                s += part[kss * G4H + bred * 128 + g * 32 + jj];
            gsum[g] = s;
        }
        float ig = sigf(gsum[0]);
        float fg = sigf(gsum[1]);
        float gg = tanhf(gsum[2]);
        float og = sigf(gsum[3]);
        c = fg * c + ig * gg;
        float h = og * tanhf(c);

        if (t == NSTEP - 1) {
            g_h[0][b0 + bred][j0 + jj] = h;
        } else {
            // push h into hsh[q][bred][j0+jj] of ALL 8 cluster CTAs
            uint32_t laddr = hsh_base
                + (uint32_t)(q * 8 * Hdim + bred * Hdim + j0 + jj) * 4u;
#pragma unroll
            for (uint32_t r = 0; r < 8; r++) {
                uint32_t ra;
                asm volatile("mapa.shared::cluster.u32 %0, %1, %2;"
                             : "=r"(ra) : "r"(laddr), "r"(r));
                asm volatile("st.shared::cluster.f32 [%0], %1;"
                             :: "r"(ra), "f"(h) : "memory");
            }
            __syncthreads();                   // all local pushes issued
            if (tid == 0) {
                asm volatile("fence.acq_rel.cluster;" ::: "memory");
                uint32_t mb = mbar_base + (uint32_t)q * 8u;
#pragma unroll
                for (uint32_t r = 0; r < 8; r++) {
                    uint32_t ra;
                    asm volatile("mapa.shared::cluster.u32 %0, %1, %2;"
                                 : "=r"(ra) : "r"(mb), "r"(r));
                    asm volatile(
                        "mbarrier.arrive.shared::cluster.b64 _, [%0];"
                        :: "r"(ra) : "memory");
                }
            }
            // wait for all 8 contributions for next step
            {
                uint32_t mb = mbar_base + (uint32_t)q * 8u;
                uint32_t phase = (uint32_t)(q ? ph1 : ph0);
                uint32_t done;
                do {
                    asm volatile(
                        "{\n\t.reg .pred p;\n\t"
                        "mbarrier.try_wait.parity.acquire.cluster.shared::cta.b64 "
                        "p, [%1], %2, 0x989680;\n\t"
                        "selp.b32 %0, 1, 0, p;\n\t}"
                        : "=r"(done) : "r"(mb), "r"(phase) : "memory");
                } while (!done);
                if (q) ph1 ^= 1; else ph0 ^= 1;
            }
        }
    }

    // keep cluster smem mapped until everyone is done
    asm volatile("barrier.cluster.arrive.aligned;" ::: "memory");
    asm volatile("barrier.cluster.wait.aligned;"  ::: "memory");
}

// ---------------------------------------------------------------------------
// Final: hb_last = ONE backward step from zero state on x[:,T-1]
// ---------------------------------------------------------------------------
__global__ void final_k(const float* __restrict__ Wlin,
                        const float* __restrict__ blin,
                        float* __restrict__ out)
{
    int b = threadIdx.x;
    float a0 = blin[0], a1 = blin[1];
    const float* hf = &g_h[0][b][0];
#pragma unroll 4
    for (int j = 0; j < Hdim; j++) {
        float h = hf[j];
        a0 = fmaf(h, Wlin[j], a0);
        a1 = fmaf(h, Wlin[512 + j], a1);
    }
    const float* xb = &g_xpb[b * G4H];
#pragma unroll 4
    for (int j = 0; j < Hdim; j++) {
        float ig = 1.f / (1.f + __expf(-xb[j]));
        float gg = tanhf(xb[512 + j]);
        float og = 1.f / (1.f + __expf(-xb[768 + j]));
        float cc = ig * gg;
        float h  = og * tanhf(cc);
        a0 = fmaf(h, Wlin[256 + j], a0);
        a1 = fmaf(h, Wlin[768 + j], a1);
    }
    out[b * 2]     = a0;
    out[b * 2 + 1] = a1;
}

// ---------------------------------------------------------------------------
// launch
// ---------------------------------------------------------------------------
extern "C" void kernel_launch(void* const* d_in, const int* in_sizes, int n_in,
                              void* d_out, int out_size)
{
    const float* x    = (const float*)d_in[0];
    const float* Wihf = (const float*)d_in[1];
    const float* Whhf = (const float*)d_in[2];
    const float* bf   = (const float*)d_in[3];
    const float* Wihb = (const float*)d_in[4];
    // d_in[5] = W_hh_b: unused (backward output only needs its first step)
    const float* bb   = (const float*)d_in[6];
    const float* Wlin = (const float*)d_in[7];
    const float* blin = (const float*)d_in[8];
    float* out = (float*)d_out;

    void *xp_ptr = nullptr, *xpb_ptr = nullptr;
    void *ah = nullptr, *al = nullptr, *bh = nullptr, *bl = nullptr;
    cudaGetSymbolAddress(&xp_ptr,  g_xp);
    cudaGetSymbolAddress(&xpb_ptr, g_xpb);
    cudaGetSymbolAddress(&ah, g_Ah);
    cudaGetSymbolAddress(&al, g_Al);
    cudaGetSymbolAddress(&bh, g_Bh);
    cudaGetSymbolAddress(&bl, g_Bl);

    cudaFuncSetAttribute(gemm_wmma, cudaFuncAttributeMaxDynamicSharedMemorySize,
                         GEMM_SMEM);
    cudaFuncSetAttribute(lstm_fwd, cudaFuncAttributeMaxDynamicSharedMemorySize,
                         SMEM_BYTES);

    init_k<<<128, 256>>>();

    // split-bf16 operand packing (plain linear tiles)
    conv_pack<<<(65536 * 40 + 255) / 256, 256>>>(x, 65536, (uint4*)ah, (uint4*)al);
    conv_pack<<<(1024 * 40 + 255) / 256, 256>>>(Wihf, 1024, (uint4*)bh, (uint4*)bl);

    // xp_f = x @ W_ih_f^T on HMMA tensor path
    gemm_wmma<<<dim3(8, 512), 256, GEMM_SMEM>>>(
        (const uint4*)ah, (const uint4*)al, (const uint4*)bh, (const uint4*)bl,
        (float*)xp_ptr);

    // backward projection at t = T-1 only (tiny, fp32, bias included)
    sgemm_bias<<<dim3(8, 1), 256>>>(x + (long)(Tdim - 1) * Idim,
                                    (long)Tdim * Idim, Wihb, bb,
                                    (float*)xpb_ptr);

    // persistent FFMA recurrence, cluster DSMEM h-exchange
    lstm_fwd<<<128, 256, SMEM_BYTES>>>(Whhf, bf);

    // epilogue
    final_k<<<1, 128>>>(Wlin, blin, out);
}

// round 15
// speedup vs baseline: 1.2956x; 1.2956x over previous
#include <cuda_runtime.h>
#include <cuda_bf16.h>
#include <mma.h>
#include <math.h>
#include <stdint.h>

using namespace nvcuda;

#define Bdim 128
#define Tdim 512
#define Idim 300
#define Hdim 256
#define G4H  1024   // 4*H gate rows
#define NSTEP 512

#define KBLK 5      // K padded 300 -> 320 = 5 blocks of 64 bf16
#define GPITCH 72   // smem pitch (bf16 elems) for gemm_wmma tiles

// ---------------------------------------------------------------------------
// Scratch (static __device__ globals; no allocation anywhere)
// ---------------------------------------------------------------------------
__device__ float g_xp[(size_t)Bdim * Tdim * G4H];   // 256 MB: x @ W_ih_f^T (no bias)
__device__ float g_xpb[Bdim * G4H];                 // backward projection at t=T-1
__device__ float g_h[2][Bdim][Hdim];                // double-buffered hidden state
__device__ unsigned int g_bar[16];                  // per-batch-group barrier counters

// packed bf16 hi/lo operand tiles, plain linear layout:
__device__ uint4 g_Ah[(size_t)512 * KBLK * 1024];
__device__ uint4 g_Al[(size_t)512 * KBLK * 1024];
__device__ uint4 g_Bh[8 * KBLK * 1024];
__device__ uint4 g_Bl[8 * KBLK * 1024];

// ---------------------------------------------------------------------------
__global__ void init_k()
{
    int i = blockIdx.x * blockDim.x + threadIdx.x;
    if (i < Bdim * Hdim) ((float*)g_h)[i] = 0.f;
    if (i < 16) g_bar[i] = 0u;
}

// ---------------------------------------------------------------------------
// conv_pack: fp32 rows [rows x Idim] -> bf16 hi/lo packed tiles (linear).
// ---------------------------------------------------------------------------
__global__ void conv_pack(const float* __restrict__ src, int rows,
                          uint4* __restrict__ Hc, uint4* __restrict__ Lc)
{
    int id = blockIdx.x * blockDim.x + threadIdx.x;
    int total = rows * 40;
    if (id >= total) return;
    int m  = id / 40;
    int g  = id % 40;
    int k0 = g * 8;

    union U8 { uint4 u; __nv_bfloat16 b[8]; } hu, lu;
#pragma unroll
    for (int j = 0; j < 8; j++) {
        int k = k0 + j;
        float v = (k < Idim) ? src[(size_t)m * Idim + k] : 0.f;
        __nv_bfloat16 h = __float2bfloat16(v);
        hu.b[j] = h;
        lu.b[j] = __float2bfloat16(v - __bfloat162float(h));
    }

    int tile = m >> 7;
    int r    = m & 127;
    int blk  = k0 >> 6;
    int c8   = (k0 & 63) >> 3;
    size_t idx = ((size_t)tile * KBLK + blk) * 1024 + (size_t)r * 8 + c8;
    Hc[idx] = hu.u;
    Lc[idx] = lu.u;
}

// ---------------------------------------------------------------------------
// gemm_wmma — EXACT R6 version (490 us): xp = x @ W_ih_f^T, split-bf16 HMMA
// ---------------------------------------------------------------------------
#define GEMM_SMEM (4 * 128 * GPITCH * 2)

__global__ void __launch_bounds__(256) gemm_wmma(
    const uint4* __restrict__ Ah, const uint4* __restrict__ Al,
    const uint4* __restrict__ Bh, const uint4* __restrict__ Bl,
    float* __restrict__ C)
{
    extern __shared__ __nv_bfloat16 sm[];
    __nv_bfloat16* sAh = sm;
    __nv_bfloat16* sAl = sm + 128 * GPITCH;
    __nv_bfloat16* sBh = sm + 2 * 128 * GPITCH;
    __nv_bfloat16* sBl = sm + 3 * 128 * GPITCH;

    int tid = threadIdx.x;
    int wid = tid >> 5;
    int wm  = wid >> 2;
    int wn  = wid & 3;
    int nt  = blockIdx.x;
    int mt  = blockIdx.y;

    wmma::fragment<wmma::accumulator, 16, 16, 16, float> acc[4][2];
#pragma unroll
    for (int i = 0; i < 4; i++)
#pragma unroll
        for (int j = 0; j < 2; j++) wmma::fill_fragment(acc[i][j], 0.f);

    for (int blk = 0; blk < KBLK; blk++) {
        const uint4* gA_h = Ah + ((size_t)mt * KBLK + blk) * 1024;
        const uint4* gA_l = Al + ((size_t)mt * KBLK + blk) * 1024;
        const uint4* gB_h = Bh + ((size_t)nt * KBLK + blk) * 1024;
        const uint4* gB_l = Bl + ((size_t)nt * KBLK + blk) * 1024;
        uint4* dAh = (uint4*)sAh;
        uint4* dAl = (uint4*)sAl;
        uint4* dBh = (uint4*)sBh;
        uint4* dBl = (uint4*)sBl;
#pragma unroll
        for (int it = 0; it < 4; it++) {
            int i = it * 256 + tid;
            int r = i >> 3, c = i & 7;
            int d = r * 9 + c;
            dAh[d] = gA_h[i];
            dAl[d] = gA_l[i];
            dBh[d] = gB_h[i];
            dBl[d] = gB_l[i];
        }
        __syncthreads();

#pragma unroll
        for (int prod = 0; prod < 3; prod++) {
            const __nv_bfloat16* As = (prod == 2) ? sAl : sAh;
            const __nv_bfloat16* Bs = (prod == 1) ? sBl : sBh;
#pragma unroll
            for (int ks = 0; ks < 4; ks++) {
                wmma::fragment<wmma::matrix_a, 16, 16, 16, __nv_bfloat16,
                               wmma::row_major> af[4];
                wmma::fragment<wmma::matrix_b, 16, 16, 16, __nv_bfloat16,
                               wmma::col_major> bfr[2];
#pragma unroll
                for (int i = 0; i < 4; i++)
                    wmma::load_matrix_sync(
                        af[i], As + (wm * 64 + i * 16) * GPITCH + ks * 16, GPITCH);
#pragma unroll
                for (int j = 0; j < 2; j++)
                    wmma::load_matrix_sync(
                        bfr[j], Bs + (wn * 32 + j * 16) * GPITCH + ks * 16, GPITCH);
#pragma unroll
                for (int i = 0; i < 4; i++)
#pragma unroll
                    for (int j = 0; j < 2; j++)
                        wmma::mma_sync(acc[i][j], af[i], bfr[j], acc[i][j]);
            }
        }
        __syncthreads();
    }

    size_t row0 = (size_t)mt * 128 + wm * 64;
    int    col0 = nt * 128 + wn * 32;
#pragma unroll
    for (int i = 0; i < 4; i++)
#pragma unroll
        for (int j = 0; j < 2; j++)
            wmma::store_matrix_sync(
                C + (row0 + i * 16) * G4H + col0 + j * 16,
                acc[i][j], G4H, wmma::mem_row_major);
}

// ---------------------------------------------------------------------------
// fp32 SGEMM (tiny backward projection at t = T-1; includes bias)
// ---------------------------------------------------------------------------
__global__ void __launch_bounds__(256) sgemm_bias(
    const float* __restrict__ A, long lda,
    const float* __restrict__ W,
    const float* __restrict__ bias,
    float* __restrict__ C)
{
    __shared__ float As[8][128];
    __shared__ float Bs[8][128];
    int tid  = threadIdx.x;
    long row0 = (long)blockIdx.y * 128;
    int  col0 = blockIdx.x * 128;
    int  lm = tid >> 1;
    int  lk = (tid & 1) * 4;
    int  tx = tid & 15, ty = tid >> 4;

    float bsv[8];
    *(float4*)(bsv)     = *(const float4*)&bias[col0 + tx * 8];
    *(float4*)(bsv + 4) = *(const float4*)&bias[col0 + tx * 8 + 4];

    float acc[8][8];
#pragma unroll
    for (int i = 0; i < 8; i++)
#pragma unroll
        for (int j = 0; j < 8; j++) acc[i][j] = 0.f;

    for (int k0 = 0; k0 < Idim; k0 += 8) {
        float4 av = make_float4(0.f, 0.f, 0.f, 0.f);
        float4 bv = make_float4(0.f, 0.f, 0.f, 0.f);
        if (k0 + lk < Idim) {
            av = *(const float4*)(A + (row0 + lm) * lda + k0 + lk);
            bv = *(const float4*)(W + (long)(col0 + lm) * Idim + k0 + lk);
        }
        __syncthreads();
        As[lk + 0][lm] = av.x; As[lk + 1][lm] = av.y;
        As[lk + 2][lm] = av.z; As[lk + 3][lm] = av.w;
        Bs[lk + 0][lm] = bv.x; Bs[lk + 1][lm] = bv.y;
        Bs[lk + 2][lm] = bv.z; Bs[lk + 3][lm] = bv.w;
        __syncthreads();
#pragma unroll
        for (int k = 0; k < 8; k++) {
            float a[8], b[8];
            *(float4*)(a)     = *(const float4*)&As[k][ty * 8];
            *(float4*)(a + 4) = *(const float4*)&As[k][ty * 8 + 4];
            *(float4*)(b)     = *(const float4*)&Bs[k][tx * 8];
            *(float4*)(b + 4) = *(const float4*)&Bs[k][tx * 8 + 4];
#pragma unroll
            for (int i = 0; i < 8; i++)
#pragma unroll
                for (int j = 0; j < 8; j++)
                    acc[i][j] = fmaf(a[i], b[j], acc[i][j]);
        }
    }

#pragma unroll
    for (int i = 0; i < 8; i++) {
        long r = row0 + ty * 8 + i;
        float4 o0 = make_float4(acc[i][0] + bsv[0], acc[i][1] + bsv[1],
                                acc[i][2] + bsv[2], acc[i][3] + bsv[3]);
        float4 o1 = make_float4(acc[i][4] + bsv[4], acc[i][5] + bsv[5],
                                acc[i][6] + bsv[6], acc[i][7] + bsv[7]);
        *(float4*)&C[r * G4H + col0 + tx * 8]     = o0;
        *(float4*)&C[r * G4H + col0 + tx * 8 + 4] = o1;
    }
}

// ---------------------------------------------------------------------------
// Persistent forward LSTM recurrence — EXACT R6 compute structure; ONLY the
// group barrier is reworked:
//   producer: __syncthreads -> tid0 { membar.gl ; red.relaxed.gpu.add }
//   consumer: ALL threads poll ld.acquire.gpu (coalesced; nanosleep backoff);
//             no trailing syncthreads (next iter's h-copy sync realigns)
// ---------------------------------------------------------------------------
#define WPITCH 129
#define SMEM_FLOATS (Hdim * WPITCH + 8 * Hdim + 8 * G4H)
#define SMEM_BYTES  (SMEM_FLOATS * 4)

__device__ __forceinline__ float sigf(float x) { return 1.f / (1.f + __expf(-x)); }

__global__ void __launch_bounds__(256, 1) lstm_fwd(const float* __restrict__ Whh,
                                                   const float* __restrict__ bias)
{
    extern __shared__ float sm_f[];
    float* Wsh  = sm_f;                       // [256][129] transposed W tile
    float* hsh  = sm_f + Hdim * WPITCH;       // [8][256]   h for this batch tile
    float* part = hsh + 8 * Hdim;             // [8][1024]  k-split partials

    int tid = threadIdx.x;
    int gb  = blockIdx.x >> 3;
    int gj  = blockIdx.x & 7;
    int b0  = gb * 8;
    int j0  = gj * 32;

    for (int idx = tid; idx < 128 * Hdim; idx += 256) {
        int lr = idx >> 8;
        int k  = idx & 255;
        int grow = ((lr >> 5) << 8) + j0 + (lr & 31);
        Wsh[k * WPITCH + lr] = Whh[grow * Hdim + k];
    }

    int ks    = tid >> 5;
    int lane  = tid & 31;
    int bg    = lane >> 4;
    int r8    = lane & 15;
    int kbase = ks * 32;
    int bred  = tid >> 5;
    int jj    = tid & 31;

    float bgate[4];
#pragma unroll
    for (int g = 0; g < 4; g++) bgate[g] = bias[g * 256 + j0 + jj];

    float c = 0.f;
    unsigned int* barp = &g_bar[gb];
    __syncthreads();

    for (int t = 0; t < NSTEP; t++) {
        float xg[4];
        {
            size_t base = ((size_t)(b0 + bred) * Tdim + t) * G4H + j0 + jj;
#pragma unroll
            for (int g = 0; g < 4; g++) xg[g] = g_xp[base + (size_t)g * 256];
        }

        int p = t & 1;
        {
            const float4* src = (const float4*)&g_h[p][b0][0];
            float4* dst = (float4*)hsh;
            for (int i = tid; i < 512; i += 256) dst[i] = src[i];
        }
        __syncthreads();

        float acc[4][8];
#pragma unroll
        for (int bi = 0; bi < 4; bi++)
#pragma unroll
            for (int i = 0; i < 8; i++) acc[bi][i] = 0.f;

#pragma unroll
        for (int k = 0; k < 32; k += 4) {
            float4 hv[4];
#pragma unroll
            for (int bi = 0; bi < 4; bi++)
                hv[bi] = *(const float4*)&hsh[(bg * 4 + bi) * Hdim + kbase + k];
#pragma unroll
            for (int kk = 0; kk < 4; kk++) {
                const float* wr = &Wsh[(kbase + k + kk) * WPITCH + r8];
                float w[8];
#pragma unroll
                for (int i = 0; i < 8; i++) w[i] = wr[i * 16];
#pragma unroll
                for (int bi = 0; bi < 4; bi++) {
                    float hval = ((const float*)&hv[bi])[kk];
#pragma unroll
                    for (int i = 0; i < 8; i++)
                        acc[bi][i] = fmaf(hval, w[i], acc[bi][i]);
                }
            }
        }

#pragma unroll
        for (int bi = 0; bi < 4; bi++)
#pragma unroll
            for (int i = 0; i < 8; i++)
                part[ks * G4H + (bg * 4 + bi) * 128 + (r8 + 16 * i)] = acc[bi][i];
        __syncthreads();

        float gsum[4];
#pragma unroll
        for (int g = 0; g < 4; g++) {
            float s = xg[g] + bgate[g];
#pragma unroll
            for (int kss = 0; kss < 8; kss++)
                s += part[kss * G4H + bred * 128 + g * 32 + jj];
            gsum[g] = s;
        }
        float ig = sigf(gsum[0]);
        float fg = sigf(gsum[1]);
        float gg = tanhf(gsum[2]);
        float og = sigf(gsum[3]);
        c = fg * c + ig * gg;
        float h = og * tanhf(c);
        g_h[p ^ 1][b0 + bred][j0 + jj] = h;
        __syncthreads();

        // ---- lightweight group barrier (only change vs the 3154 kernel) ----
        if (t < NSTEP - 1) {
            if (tid == 0) {
                asm volatile("membar.gl;" ::: "memory");
                asm volatile("red.relaxed.gpu.global.add.u32 [%0], 1;"
                             :: "l"(barp) : "memory");
            }
            unsigned target = 8u * (unsigned)(t + 1);
            unsigned v;
            asm volatile("ld.acquire.gpu.global.u32 %0, [%1];"
                         : "=r"(v) : "l"(barp) : "memory");
            while (v < target) {
                __nanosleep(200);
                asm volatile("ld.acquire.gpu.global.u32 %0, [%1];"
                             : "=r"(v) : "l"(barp) : "memory");
            }
            // no trailing __syncthreads: next iteration's h-copy sync realigns
        }
    }
}

// ---------------------------------------------------------------------------
// Final: hb_last = ONE backward step from zero state on x[:,T-1]
// ---------------------------------------------------------------------------
__global__ void final_k(const float* __restrict__ Wlin,
                        const float* __restrict__ blin,
                        float* __restrict__ out)
{
    int b = threadIdx.x;
    float a0 = blin[0], a1 = blin[1];
    const float* hf = &g_h[0][b][0];
#pragma unroll 4
    for (int j = 0; j < Hdim; j++) {
        float h = hf[j];
        a0 = fmaf(h, Wlin[j], a0);
        a1 = fmaf(h, Wlin[512 + j], a1);
    }
    const float* xb = &g_xpb[b * G4H];
#pragma unroll 4
    for (int j = 0; j < Hdim; j++) {
        float ig = 1.f / (1.f + __expf(-xb[j]));
        float gg = tanhf(xb[512 + j]);
        float og = 1.f / (1.f + __expf(-xb[768 + j]));
        float cc = ig * gg;
        float h  = og * tanhf(cc);
        a0 = fmaf(h, Wlin[256 + j], a0);
        a1 = fmaf(h, Wlin[768 + j], a1);
    }
    out[b * 2]     = a0;
    out[b * 2 + 1] = a1;
}

// ---------------------------------------------------------------------------
// launch
// ---------------------------------------------------------------------------
extern "C" void kernel_launch(void* const* d_in, const int* in_sizes, int n_in,
                              void* d_out, int out_size)
{
    const float* x    = (const float*)d_in[0];
    const float* Wihf = (const float*)d_in[1];
    const float* Whhf = (const float*)d_in[2];
    const float* bf   = (const float*)d_in[3];
    const float* Wihb = (const float*)d_in[4];
    // d_in[5] = W_hh_b: unused (backward output only needs its first step)
    const float* bb   = (const float*)d_in[6];
    const float* Wlin = (const float*)d_in[7];
    const float* blin = (const float*)d_in[8];
    float* out = (float*)d_out;

    void *xp_ptr = nullptr, *xpb_ptr = nullptr;
    void *ah = nullptr, *al = nullptr, *bh = nullptr, *bl = nullptr;
    cudaGetSymbolAddress(&xp_ptr,  g_xp);
    cudaGetSymbolAddress(&xpb_ptr, g_xpb);
    cudaGetSymbolAddress(&ah, g_Ah);
    cudaGetSymbolAddress(&al, g_Al);
    cudaGetSymbolAddress(&bh, g_Bh);
    cudaGetSymbolAddress(&bl, g_Bl);

    cudaFuncSetAttribute(gemm_wmma, cudaFuncAttributeMaxDynamicSharedMemorySize,
                         GEMM_SMEM);
    cudaFuncSetAttribute(lstm_fwd, cudaFuncAttributeMaxDynamicSharedMemorySize,
                         SMEM_BYTES);

    init_k<<<128, 256>>>();

    // split-bf16 operand packing (plain linear tiles)
    conv_pack<<<(65536 * 40 + 255) / 256, 256>>>(x, 65536, (uint4*)ah, (uint4*)al);
    conv_pack<<<(1024 * 40 + 255) / 256, 256>>>(Wihf, 1024, (uint4*)bh, (uint4*)bl);

    // xp_f = x @ W_ih_f^T on HMMA tensor path
    gemm_wmma<<<dim3(8, 512), 256, GEMM_SMEM>>>(
        (const uint4*)ah, (const uint4*)al, (const uint4*)bh, (const uint4*)bl,
        (float*)xp_ptr);

    // backward projection at t = T-1 only (tiny, fp32, bias included)
    sgemm_bias<<<dim3(8, 1), 256>>>(x + (long)(Tdim - 1) * Idim,
                                    (long)Tdim * Idim, Wihb, bb,
                                    (float*)xpb_ptr);

    // persistent FFMA recurrence (lightweight group barrier)
    lstm_fwd<<<128, 256, SMEM_BYTES>>>(Whhf, bf);

    // epilogue
    final_k<<<1, 128>>>(Wlin, blin, out);
}